// round 10
// baseline (speedup 1.0000x reference)
#include <cuda_runtime.h>
#include <stdint.h>

// Shapes (fixed by the problem)
#define B_  32
#define S_  4096
#define H_  2048
#define ADAPT_ 32
#define RANK_ 16
#define K_ 8

#define SSPLIT 16                 // S chunks of 256 rows
#define ROWS_PER (S_ / SSPLIT)    // 256
#define NBLOCKS (SSPLIT * B_)     // 512

// Static scratch (no allocations allowed)
__device__ float g_colsum[B_ * SSPLIT * H_];   // 4 MB per-block column sums
__device__ float g_hpre[B_ * ADAPT_];          // pre-LN features
__device__ unsigned g_cnt_b[B_];               // per-batch counters (self-reset)
__device__ unsigned g_count = 0;               // global fold counter (self-reset)

// ---------------------------------------------------------------------------
// Threefry2x32 (JAX default PRNG), 20 rounds.
// ---------------------------------------------------------------------------
__device__ __forceinline__ uint32_t rotl32(uint32_t x, int d) {
    return (x << d) | (x >> (32 - d));
}

__device__ __forceinline__ uint2 threefry2x32(uint32_t k0, uint32_t k1,
                                              uint32_t x0, uint32_t x1) {
    const uint32_t k2 = k0 ^ k1 ^ 0x1BD11BDAu;
    const int R0[4] = {13, 15, 26, 6};
    const int R1[4] = {17, 29, 16, 24};
    x0 += k0; x1 += k1;
#pragma unroll
    for (int r = 0; r < 4; ++r) { x0 += x1; x1 = rotl32(x1, R0[r]); x1 ^= x0; }
    x0 += k1; x1 += k2 + 1u;
#pragma unroll
    for (int r = 0; r < 4; ++r) { x0 += x1; x1 = rotl32(x1, R1[r]); x1 ^= x0; }
    x0 += k2; x1 += k0 + 2u;
#pragma unroll
    for (int r = 0; r < 4; ++r) { x0 += x1; x1 = rotl32(x1, R0[r]); x1 ^= x0; }
    x0 += k0; x1 += k1 + 3u;
#pragma unroll
    for (int r = 0; r < 4; ++r) { x0 += x1; x1 = rotl32(x1, R1[r]); x1 ^= x0; }
    x0 += k1; x1 += k2 + 4u;
#pragma unroll
    for (int r = 0; r < 4; ++r) { x0 += x1; x1 = rotl32(x1, R0[r]); x1 ^= x0; }
    x0 += k2; x1 += k0 + 5u;
    return make_uint2(x0, x1);
}

// uniform [0,1) matching modern JAX (jax_threefry_partitionable=True):
// element i uses 64-bit counter = i; 32-bit draw = x0 ^ x1.
__device__ __forceinline__ float jax_uniform(uint32_t seed, uint32_t i) {
    uint2 r = threefry2x32(0u, seed, 0u, i);
    uint32_t bits = r.x ^ r.y;
    return __uint_as_float((bits >> 9) | 0x3F800000u) - 1.0f;
}

// ---------------------------------------------------------------------------
// Single fused kernel, staggered per-batch reduction. grid (SSPLIT, B_).
// Phase A (all 512 blocks): stream 256 contiguous rows -> column sums ->
//   write 8 KB to g_colsum, bump per-batch counter.
// Fold (last block of each batch, 32 total): reduce 16 partials (L2-hot),
//   fold through W1 -> g_hpre[b][32], bump global counter.
// Head (last fold block): LN + GELU + dropout + W2 + Gumbel top-k + softmax
//   + mask/EMA/entropy.
// out layout: [mask 32*16][ema 16][entropy 1]
// ---------------------------------------------------------------------------
__global__ __launch_bounds__(256) void k_all(const float* __restrict__ x,
                                             const float* __restrict__ W1,
                                             const float* __restrict__ b1,
                                             const float* __restrict__ ln_g,
                                             const float* __restrict__ ln_b,
                                             const float* __restrict__ W2,
                                             const float* __restrict__ b2,
                                             const float* __restrict__ mask_logits,
                                             const float* __restrict__ mask_ema,
                                             float* __restrict__ out) {
    const int split = blockIdx.x;   // 0..15
    const int b     = blockIdx.y;   // 0..31
    const int t     = threadIdx.x;  // 0..255

    // ---------------- Phase A: stream 256 contiguous rows ----------------
    {
        const float4* p = reinterpret_cast<const float4*>(x)
                        + ((size_t)b * S_ + (size_t)split * ROWS_PER) * (H_ / 4);
        float a0x = 0.f, a0y = 0.f, a0z = 0.f, a0w = 0.f;
        float a1x = 0.f, a1y = 0.f, a1z = 0.f, a1w = 0.f;
#pragma unroll 4
        for (int r = 0; r < ROWS_PER; ++r) {
            float4 v0 = p[(size_t)r * (H_ / 4) + t];
            float4 v1 = p[(size_t)r * (H_ / 4) + t + 256];
            a0x += v0.x; a0y += v0.y; a0z += v0.z; a0w += v0.w;
            a1x += v1.x; a1y += v1.y; a1z += v1.z; a1w += v1.w;
        }
        float4* s4 = reinterpret_cast<float4*>(g_colsum)
                   + ((size_t)b * SSPLIT + split) * (H_ / 4);
        s4[t]       = make_float4(a0x, a0y, a0z, a0w);
        s4[t + 256] = make_float4(a1x, a1y, a1z, a1w);
    }

    // ---------------- Per-batch completion: 16th block folds ----------------
    __threadfence();
    __syncthreads();
    __shared__ unsigned do_fold;
    if (t == 0) {
        unsigned done = atomicAdd(&g_cnt_b[b], 1u) + 1u;
        do_fold = (done == SSPLIT) ? 1u : 0u;
        if (do_fold) g_cnt_b[b] = 0u;    // reset (only this block touches it now)
    }
    __syncthreads();
    if (!do_fold) return;
    __threadfence();   // acquire: batch b's colsums visible

    // ---------------- Fold: reduce 16 splits + W1 (one block per batch) -----
    __shared__ __align__(16) float pooled[H_];
    {
        const float4* cs4 = reinterpret_cast<const float4*>(g_colsum)
                          + (size_t)b * SSPLIT * (H_ / 4);
#pragma unroll
        for (int cc = 0; cc < 2; ++cc) {
            const int c = t + 256 * cc;
            float ax = 0.f, ay = 0.f, az = 0.f, aw = 0.f;
#pragma unroll
            for (int s = 0; s < SSPLIT; ++s) {
                float4 v = cs4[(size_t)s * (H_ / 4) + c];
                ax += v.x; ay += v.y; az += v.z; aw += v.w;
            }
            reinterpret_cast<float4*>(pooled)[c] = make_float4(ax, ay, az, aw);
        }
    }
    __syncthreads();

    {
        const int a = t & 31;     // output feature
        const int g = t >> 5;     // warp 0..7, handles 256 h-rows
        float acc = 0.f;
        const int h0 = g * (H_ / 8);
#pragma unroll 8
        for (int i = 0; i < H_ / 8; ++i) {
            const int h = h0 + i;
            acc += pooled[h] * W1[(size_t)h * ADAPT_ + a];
        }
        __shared__ float part[8][ADAPT_];
        part[g][a] = acc;
        __syncthreads();

        if (t < ADAPT_) {
            float s = part[0][t];
#pragma unroll
            for (int g2 = 1; g2 < 8; ++g2) s += part[g2][t];
            g_hpre[b * ADAPT_ + t] = s * (1.0f / (float)S_) + b1[t];
        }
    }

    // ---------------- Global completion: last fold block runs head ----------
    __threadfence();
    __syncthreads();
    __shared__ unsigned is_last;
    if (t == 0) {
        unsigned done = atomicAdd(&g_count, 1u) + 1u;
        is_last = (done == B_) ? 1u : 0u;
        if (is_last) g_count = 0u;    // reset for next graph replay
    }
    __syncthreads();
    if (!is_last) return;
    __threadfence();   // acquire: all g_hpre visible

    // ---------------- Head (single block, 256 threads) ----------------
    const int lane = t & 31;
    const int w    = t >> 5;

    __shared__ float hsm[B_][ADAPT_];
    {
        // load hpre: thread loads one float4
        const int bC = t >> 3;
        const int a4 = t & 7;
        float4 v = reinterpret_cast<const float4*>(g_hpre)[bC * (ADAPT_ / 4) + a4];
        hsm[bC][4 * a4 + 0] = v.x;
        hsm[bC][4 * a4 + 1] = v.y;
        hsm[bC][4 * a4 + 2] = v.z;
        hsm[bC][4 * a4 + 3] = v.w;
    }
    __syncthreads();

    // LN + GELU + dropout. Warp w handles batch rows 4w..4w+3.
#pragma unroll
    for (int bb = 0; bb < 4; ++bb) {
        const int bL = 4 * w + bb;
        float h = hsm[bL][lane];

        float m = h;
#pragma unroll
        for (int o = 16; o; o >>= 1) m += __shfl_xor_sync(0xFFFFFFFFu, m, o);
        m *= (1.0f / 32.0f);
        float d = h - m;
        float v = d * d;
#pragma unroll
        for (int o = 16; o; o >>= 1) v += __shfl_xor_sync(0xFFFFFFFFu, v, o);
        v *= (1.0f / 32.0f);
        h = d * rsqrtf(v + 1e-5f) * ln_g[lane] + ln_b[lane];

        // exact GELU
        h = 0.5f * h * (1.0f + erff(h * 0.70710678118654752f));

        // Dropout(0.1), key(1), shape (32,32), flat index bL*32+lane
        float u = jax_uniform(1u, (uint32_t)(bL * ADAPT_ + lane));
        h = (u >= 0.1f) ? h * (1.0f / 0.9f) : 0.0f;

        hsm[bL][lane] = h;
    }
    __syncthreads();

    // logits + Gumbel. Thread (bC = t>>3, jj = t&7) handles j = jj, jj+8.
    __shared__ float comb[B_][RANK_];
    __shared__ float pert[B_][RANK_];
    {
        const int bC = t >> 3;
        const int jj = t & 7;
#pragma unroll
        for (int r = 0; r < 2; ++r) {
            const int j = jj + 8 * r;
            float acc = b2[j] + mask_logits[j];
#pragma unroll
            for (int a = 0; a < ADAPT_; ++a) acc += hsm[bC][a] * W2[a * RANK_ + j];
            comb[bC][j] = acc;

            float u = jax_uniform(2u, (uint32_t)(bC * RANK_ + j));
            float gmb = -logf(-logf(u + 1e-8f) + 1e-8f);
            pert[bC][j] = acc + gmb;
        }
    }
    __syncthreads();

    // top-k rank, softmax, straight-through mask.
    __shared__ float maskv[B_][RANK_];
    {
        const int bC = t >> 3;
        const int jj = t & 7;

        float mx = -1e30f;
#pragma unroll
        for (int m2 = 0; m2 < RANK_; ++m2) mx = fmaxf(mx, comb[bC][m2]);
        float ssum = 0.0f;
#pragma unroll
        for (int m2 = 0; m2 < RANK_; ++m2) ssum += expf((comb[bC][m2] - mx) * 10.0f);

#pragma unroll
        for (int r = 0; r < 2; ++r) {
            const int j = jj + 8 * r;
            const float vj = pert[bC][j];
            int rank = 0;
#pragma unroll
            for (int m2 = 0; m2 < RANK_; ++m2) {
                float vm = pert[bC][m2];
                rank += (vm > vj) || (vm == vj && m2 < j);
            }
            float khot = (rank < K_) ? 1.0f : 0.0f;
            float soft = expf((comb[bC][j] - mx) * 10.0f) / ssum;

            float mv = (khot + soft) - soft;   // straight-through forward
            maskv[bC][j] = mv;
            out[bC * RANK_ + j] = mv;
        }
    }
    __syncthreads();

    // EMA + entropy (threads 0..15, all in warp 0).
    if (t < RANK_) {
        float s = 0.0f;
#pragma unroll
        for (int bb = 0; bb < B_; ++bb) s += maskv[bb][t];
        float ema = 0.99f * mask_ema[t] + 0.01f * (s * (1.0f / (float)B_));
        out[B_ * RANK_ + t] = ema;

        __shared__ float esm[RANK_];
        esm[t] = ema * logf(ema + 1e-8f);
        __syncwarp(0x0000FFFFu);
        if (t == 0) {
            float tot = 0.0f;
#pragma unroll
            for (int j = 0; j < RANK_; ++j) tot += esm[j];
            out[B_ * RANK_ + RANK_] = -tot;
        }
    }
}

// ---------------------------------------------------------------------------
extern "C" void kernel_launch(void* const* d_in, const int* in_sizes, int n_in,
                              void* d_out, int out_size) {
    const float* hidden      = (const float*)d_in[0];
    const float* W1          = (const float*)d_in[1];
    const float* b1          = (const float*)d_in[2];
    const float* ln_g        = (const float*)d_in[3];
    const float* ln_b        = (const float*)d_in[4];
    const float* W2          = (const float*)d_in[5];
    const float* b2          = (const float*)d_in[6];
    const float* mask_logits = (const float*)d_in[7];
    const float* mask_ema    = (const float*)d_in[8];
    float* out = (float*)d_out;

    dim3 g(SSPLIT, B_);
    k_all<<<g, 256>>>(hidden, W1, b1, ln_g, ln_b, W2, b2,
                      mask_logits, mask_ema, out);
}

// round 11
// speedup vs baseline: 1.0548x; 1.0548x over previous
#include <cuda_runtime.h>
#include <stdint.h>

// Shapes (fixed by the problem)
#define B_  32
#define S_  4096
#define H_  2048
#define ADAPT_ 32
#define RANK_ 16
#define K_ 8

#define SSPLIT 16                 // S chunks of 256 rows; also #chunks of 128 cols
#define ROWS_PER (S_ / SSPLIT)    // 256
#define CH_COLS (H_ / SSPLIT)     // 128
#define NBLOCKS (SSPLIT * B_)     // 512

// Static scratch (no allocations allowed)
__device__ float g_colsum[B_ * SSPLIT * H_];      // 4 MB per-block column sums
__device__ float g_part2[B_ * SSPLIT * ADAPT_];   // 64 KB partial projections
__device__ unsigned g_cnt_b[B_];                  // per-batch arrival counters
__device__ unsigned g_go_b[B_];                   // per-batch release flags
__device__ unsigned g_count = 0;                  // global completion counter

// ---------------------------------------------------------------------------
// Threefry2x32 (JAX default PRNG), 20 rounds.
// ---------------------------------------------------------------------------
__device__ __forceinline__ uint32_t rotl32(uint32_t x, int d) {
    return (x << d) | (x >> (32 - d));
}

__device__ __forceinline__ uint2 threefry2x32(uint32_t k0, uint32_t k1,
                                              uint32_t x0, uint32_t x1) {
    const uint32_t k2 = k0 ^ k1 ^ 0x1BD11BDAu;
    const int R0[4] = {13, 15, 26, 6};
    const int R1[4] = {17, 29, 16, 24};
    x0 += k0; x1 += k1;
#pragma unroll
    for (int r = 0; r < 4; ++r) { x0 += x1; x1 = rotl32(x1, R0[r]); x1 ^= x0; }
    x0 += k1; x1 += k2 + 1u;
#pragma unroll
    for (int r = 0; r < 4; ++r) { x0 += x1; x1 = rotl32(x1, R1[r]); x1 ^= x0; }
    x0 += k2; x1 += k0 + 2u;
#pragma unroll
    for (int r = 0; r < 4; ++r) { x0 += x1; x1 = rotl32(x1, R0[r]); x1 ^= x0; }
    x0 += k0; x1 += k1 + 3u;
#pragma unroll
    for (int r = 0; r < 4; ++r) { x0 += x1; x1 = rotl32(x1, R1[r]); x1 ^= x0; }
    x0 += k1; x1 += k2 + 4u;
#pragma unroll
    for (int r = 0; r < 4; ++r) { x0 += x1; x1 = rotl32(x1, R0[r]); x1 ^= x0; }
    x0 += k2; x1 += k0 + 5u;
    return make_uint2(x0, x1);
}

// uniform [0,1) matching modern JAX (jax_threefry_partitionable=True):
// element i uses 64-bit counter = i; 32-bit draw = x0 ^ x1.
__device__ __forceinline__ float jax_uniform(uint32_t seed, uint32_t i) {
    uint2 r = threefry2x32(0u, seed, 0u, i);
    uint32_t bits = r.x ^ r.y;
    return __uint_as_float((bits >> 9) | 0x3F800000u) - 1.0f;
}

// ---------------------------------------------------------------------------
// Single fused kernel, per-batch staggered barriers + fine-grained fold.
// grid (SSPLIT, B_) = 512 blocks x 256 threads (all resident: <=4 blocks/SM).
// Phase A: stream 256 contiguous rows -> column sums -> g_colsum[b][split].
// Per-batch barrier: 16th arriver of batch b releases g_go_b[b].
// Phase B: block (split,b) reduces chunk=split across batch b's 16 colsums,
//   folds through 128 W1 rows -> g_part2[b][chunk][32].  (R8's work split.)
// Head: global counter; last block resets sync state and runs LN/GELU/dropout
//   /W2/Gumbel top-k/softmax/mask/EMA/entropy.
// out layout: [mask 32*16][ema 16][entropy 1]
// ---------------------------------------------------------------------------
__global__ __launch_bounds__(256) void k_all(const float* __restrict__ x,
                                             const float* __restrict__ W1,
                                             const float* __restrict__ b1,
                                             const float* __restrict__ ln_g,
                                             const float* __restrict__ ln_b,
                                             const float* __restrict__ W2,
                                             const float* __restrict__ b2,
                                             const float* __restrict__ mask_logits,
                                             const float* __restrict__ mask_ema,
                                             float* __restrict__ out) {
    const int split = blockIdx.x;   // 0..15
    const int b     = blockIdx.y;   // 0..31
    const int t     = threadIdx.x;  // 0..255

    // ---------------- Phase A: stream 256 contiguous rows ----------------
    {
        const float4* p = reinterpret_cast<const float4*>(x)
                        + ((size_t)b * S_ + (size_t)split * ROWS_PER) * (H_ / 4);
        float a0x = 0.f, a0y = 0.f, a0z = 0.f, a0w = 0.f;
        float a1x = 0.f, a1y = 0.f, a1z = 0.f, a1w = 0.f;
#pragma unroll 4
        for (int r = 0; r < ROWS_PER; ++r) {
            float4 v0 = p[(size_t)r * (H_ / 4) + t];
            float4 v1 = p[(size_t)r * (H_ / 4) + t + 256];
            a0x += v0.x; a0y += v0.y; a0z += v0.z; a0w += v0.w;
            a1x += v1.x; a1y += v1.y; a1z += v1.z; a1w += v1.w;
        }
        float4* s4 = reinterpret_cast<float4*>(g_colsum)
                   + ((size_t)b * SSPLIT + split) * (H_ / 4);
        s4[t]       = make_float4(a0x, a0y, a0z, a0w);
        s4[t + 256] = make_float4(a1x, a1y, a1z, a1w);
    }

    // ---------------- Per-batch barrier ----------------
    __threadfence();
    __syncthreads();
    if (t == 0) {
        unsigned arrived = atomicAdd(&g_cnt_b[b], 1u) + 1u;
        if (arrived == SSPLIT) {
            atomicExch(&g_go_b[b], 1u);               // release batch b
        } else {
            while (atomicAdd(&g_go_b[b], 0u) == 0u) { __nanosleep(32); }
        }
    }
    __syncthreads();
    __threadfence();   // acquire: batch b's colsums visible

    // ---------------- Phase B: reduce + W1 fold for (chunk=split, b) --------
    {
        const int chunk = split;
        const int sg = t >> 5;                 // 0..7 (handles s = sg, sg+8)
        const int q  = t & 31;                 // float4 col within 128-col chunk
        const int c4 = chunk * (CH_COLS / 4);  // 32 float4 per chunk

        const float4* s4 = reinterpret_cast<const float4*>(g_colsum)
                         + (size_t)b * SSPLIT * (H_ / 4);
        float4 v0 = s4[(size_t)(sg + 0) * (H_ / 4) + c4 + q];
        float4 v1 = s4[(size_t)(sg + 8) * (H_ / 4) + c4 + q];
        float ax = v0.x + v1.x, ay = v0.y + v1.y;
        float az = v0.z + v1.z, aw = v0.w + v1.w;

        __shared__ float4 red[8][32];
        red[sg][q] = make_float4(ax, ay, az, aw);
        __syncthreads();

        __shared__ __align__(16) float pooled[CH_COLS];
        if (t < 32) {
            float4 acc = red[0][t];
#pragma unroll
            for (int g = 1; g < 8; ++g) {
                float4 v = red[g][t];
                acc.x += v.x; acc.y += v.y; acc.z += v.z; acc.w += v.w;
            }
            reinterpret_cast<float4*>(pooled)[t] = acc;
        }
        __syncthreads();

        // fold through W1 rows [chunk*128, chunk*128+128)
        const int a  = t & 31;
        const int hg = t >> 5;   // 8 groups x 16 rows
        float acc2 = 0.f;
#pragma unroll
        for (int i = 0; i < CH_COLS / 8; ++i) {
            const int h = hg * (CH_COLS / 8) + i;
            acc2 += pooled[h] * W1[(size_t)(chunk * CH_COLS + h) * ADAPT_ + a];
        }
        __shared__ float part[8][ADAPT_];
        part[hg][a] = acc2;
        __syncthreads();

        if (t < 32) {
            float s = part[0][t];
#pragma unroll
            for (int g = 1; g < 8; ++g) s += part[g][t];
            g_part2[(b * SSPLIT + chunk) * ADAPT_ + t] = s;
        }
    }

    // ---------------- Global completion: last block runs the head -----------
    __threadfence();
    __syncthreads();
    __shared__ unsigned is_last;
    if (t == 0) {
        unsigned done = atomicAdd(&g_count, 1u) + 1u;
        is_last = (done == NBLOCKS) ? 1u : 0u;
    }
    __syncthreads();
    if (!is_last) return;

    if (t < B_) {                 // reset all sync state for next graph replay
        g_cnt_b[t] = 0u;
        g_go_b[t]  = 0u;
    }
    if (t == 0) g_count = 0u;
    __threadfence();

    // ---------------- Head (single block, 256 threads) ----------------
    const int lane = t & 31;
    const int w    = t >> 5;

    __shared__ float hsm[B_][ADAPT_];

    // reduce chunk partials -> hpre
    {
        const int bC = t >> 3;
        const int a4 = t & 7;
        const float4* gp = reinterpret_cast<const float4*>(g_part2);
        float ax = 0.f, ay = 0.f, az = 0.f, aw = 0.f;
#pragma unroll
        for (int c = 0; c < SSPLIT; ++c) {
            float4 v = gp[(bC * SSPLIT + c) * (ADAPT_ / 4) + a4];
            ax += v.x; ay += v.y; az += v.z; aw += v.w;
        }
        const float invS = 1.0f / (float)S_;
        hsm[bC][4 * a4 + 0] = ax * invS + b1[4 * a4 + 0];
        hsm[bC][4 * a4 + 1] = ay * invS + b1[4 * a4 + 1];
        hsm[bC][4 * a4 + 2] = az * invS + b1[4 * a4 + 2];
        hsm[bC][4 * a4 + 3] = aw * invS + b1[4 * a4 + 3];
    }
    __syncthreads();

    // LN + GELU + dropout. Warp w handles batch rows 4w..4w+3.
#pragma unroll
    for (int bb = 0; bb < 4; ++bb) {
        const int bL = 4 * w + bb;
        float h = hsm[bL][lane];

        float m = h;
#pragma unroll
        for (int o = 16; o; o >>= 1) m += __shfl_xor_sync(0xFFFFFFFFu, m, o);
        m *= (1.0f / 32.0f);
        float d = h - m;
        float v = d * d;
#pragma unroll
        for (int o = 16; o; o >>= 1) v += __shfl_xor_sync(0xFFFFFFFFu, v, o);
        v *= (1.0f / 32.0f);
        h = d * rsqrtf(v + 1e-5f) * ln_g[lane] + ln_b[lane];

        // exact GELU
        h = 0.5f * h * (1.0f + erff(h * 0.70710678118654752f));

        // Dropout(0.1), key(1), shape (32,32), flat index bL*32+lane
        float u = jax_uniform(1u, (uint32_t)(bL * ADAPT_ + lane));
        h = (u >= 0.1f) ? h * (1.0f / 0.9f) : 0.0f;

        hsm[bL][lane] = h;
    }
    __syncthreads();

    // logits + Gumbel. Thread (bC = t>>3, jj = t&7) handles j = jj, jj+8.
    __shared__ float comb[B_][RANK_];
    __shared__ float pert[B_][RANK_];
    {
        const int bC = t >> 3;
        const int jj = t & 7;
#pragma unroll
        for (int r = 0; r < 2; ++r) {
            const int j = jj + 8 * r;
            float acc = b2[j] + mask_logits[j];
#pragma unroll
            for (int a = 0; a < ADAPT_; ++a) acc += hsm[bC][a] * W2[a * RANK_ + j];
            comb[bC][j] = acc;

            float u = jax_uniform(2u, (uint32_t)(bC * RANK_ + j));
            float gmb = -logf(-logf(u + 1e-8f) + 1e-8f);
            pert[bC][j] = acc + gmb;
        }
    }
    __syncthreads();

    // top-k rank, softmax, straight-through mask.
    __shared__ float maskv[B_][RANK_];
    {
        const int bC = t >> 3;
        const int jj = t & 7;

        float mx = -1e30f;
#pragma unroll
        for (int m2 = 0; m2 < RANK_; ++m2) mx = fmaxf(mx, comb[bC][m2]);
        float ssum = 0.0f;
#pragma unroll
        for (int m2 = 0; m2 < RANK_; ++m2) ssum += expf((comb[bC][m2] - mx) * 10.0f);

#pragma unroll
        for (int r = 0; r < 2; ++r) {
            const int j = jj + 8 * r;
            const float vj = pert[bC][j];
            int rank = 0;
#pragma unroll
            for (int m2 = 0; m2 < RANK_; ++m2) {
                float vm = pert[bC][m2];
                rank += (vm > vj) || (vm == vj && m2 < j);
            }
            float khot = (rank < K_) ? 1.0f : 0.0f;
            float soft = expf((comb[bC][j] - mx) * 10.0f) / ssum;

            float mv = (khot + soft) - soft;   // straight-through forward
            maskv[bC][j] = mv;
            out[bC * RANK_ + j] = mv;
        }
    }
    __syncthreads();

    // EMA + entropy (threads 0..15, all in warp 0).
    if (t < RANK_) {
        float s = 0.0f;
#pragma unroll
        for (int bb = 0; bb < B_; ++bb) s += maskv[bb][t];
        float ema = 0.99f * mask_ema[t] + 0.01f * (s * (1.0f / (float)B_));
        out[B_ * RANK_ + t] = ema;

        __shared__ float esm[RANK_];
        esm[t] = ema * logf(ema + 1e-8f);
        __syncwarp(0x0000FFFFu);
        if (t == 0) {
            float tot = 0.0f;
#pragma unroll
            for (int j = 0; j < RANK_; ++j) tot += esm[j];
            out[B_ * RANK_ + RANK_] = -tot;
        }
    }
}

// ---------------------------------------------------------------------------
extern "C" void kernel_launch(void* const* d_in, const int* in_sizes, int n_in,
                              void* d_out, int out_size) {
    const float* hidden      = (const float*)d_in[0];
    const float* W1          = (const float*)d_in[1];
    const float* b1          = (const float*)d_in[2];
    const float* ln_g        = (const float*)d_in[3];
    const float* ln_b        = (const float*)d_in[4];
    const float* W2          = (const float*)d_in[5];
    const float* b2          = (const float*)d_in[6];
    const float* mask_logits = (const float*)d_in[7];
    const float* mask_ema    = (const float*)d_in[8];
    float* out = (float*)d_out;

    dim3 g(SSPLIT, B_);
    k_all<<<g, 256>>>(hidden, W1, b1, ln_g, ln_b, W2, b2,
                      mask_logits, mask_ema, out);
}